// round 17
// baseline (speedup 1.0000x reference)
#include <cuda_runtime.h>
#include <cuda_fp16.h>
#include <cstdint>

#define B_    16
#define CIN_  512
#define COUT_ 512
#define LAT_  512

#define XROWS  18496            // 16 * 34 * 34
#define XGUARD 64               // front zero rows
#define XTAIL  320              // tail zero rows (covers 256-row B tiles past end)
#define NT2    73               // ceil(18496/256)
#define IMG_   4624             // 68*68 halves per (b,co) interleaved image

// ---------------- device globals (allocation-free scratch) ------------------
__device__ float g_s[B_ * CIN_];
__device__ float g_wsq[COUT_ * CIN_];
__device__ float g_d[B_ * COUT_];
// interleaved blur input: [b*512+co][row 0..67][col 0..67] fp16
__device__ __align__(256) __half g_y[(size_t)B_ * COUT_ * IMG_];

__device__ __align__(256) __half g_Ah[9ull * 512 * 512];   // [tap][co][ci]
__device__ __align__(256) __half g_Xh[(size_t)(XGUARD + XROWS + XTAIL) * 512];

// tap order grouped by parity: p0={0,2,6,8} p1={1,7} p2={3,5} p3={4}
__constant__ int c_tap[9]   = {0, 2, 6, 8, 1, 7, 3, 5, 4};
// shift[t] = (kh>>1)*34 + (kw>>1), indexed by tap id
__constant__ int c_shift[9] = {0, 0, 1, 0, 0, 1, 34, 34, 35};

// ---------------- helpers ---------------------------------------------------
__device__ __forceinline__ uint32_t smem_to_u32(const void* p) {
    uint32_t a;
    asm("{ .reg .u64 t; cvta.to.shared.u64 t, %1; cvt.u32.u64 %0, t; }"
        : "=r"(a) : "l"(p));
    return a;
}
__device__ __forceinline__ void cp16(uint32_t dst, const void* src) {
    asm volatile("cp.async.cg.shared.global [%0], [%1], 16;\n"
                 :: "r"(dst), "l"(src));
}
__device__ __forceinline__ void cp_commit() {
    asm volatile("cp.async.commit_group;\n" ::: "memory");
}
__device__ __forceinline__ void cp_wait2() {
    asm volatile("cp.async.wait_group 2;\n" ::: "memory");
}
__device__ __forceinline__ void ldsm_x4(uint32_t* r, uint32_t addr) {
    asm volatile("ldmatrix.sync.aligned.m8n8.x4.shared.b16 {%0,%1,%2,%3}, [%4];"
                 : "=r"(r[0]), "=r"(r[1]), "=r"(r[2]), "=r"(r[3]) : "r"(addr));
}
__device__ __forceinline__ void mma_fp16(float* d, const uint32_t* a,
                                         const uint32_t* b) {
    asm volatile(
        "mma.sync.aligned.m16n8k16.row.col.f32.f16.f16.f32 "
        "{%0,%1,%2,%3}, {%4,%5,%6,%7}, {%8,%9}, {%0,%1,%2,%3};"
        : "+f"(d[0]), "+f"(d[1]), "+f"(d[2]), "+f"(d[3])
        : "r"(a[0]), "r"(a[1]), "r"(a[2]), "r"(a[3]), "r"(b[0]), "r"(b[1]));
}
// smem tile rows of 64 fp16 (128B), xor-swizzled 16B chunks, 8-row period
__device__ __forceinline__ int swz(int row, int c8) {
    return row * 128 + ((c8 ^ (row & 7)) << 4);
}

// ---------------------------------------------------------------------------
// Launch 1: style (blocks 0..15, warp-cooperative coalesced) +
//           prepw/wsq (blocks 16..527)
__global__ __launch_bounds__(512) void k_sw(const float* __restrict__ w,
                                            const float* __restrict__ aw,
                                            const float* __restrict__ ab,
                                            const float* __restrict__ weight) {
    const int bx = blockIdx.x, tid = threadIdx.x;
    if (bx < 16) {
        __shared__ float sw[512];
        const int b = bx;
        sw[tid] = w[b * 512 + tid];
        __syncthreads();
        const int lane = tid & 31, wp = tid >> 5;   // 16 warps x 32 ci
        for (int cc = 0; cc < 32; ++cc) {
            const int ci = wp * 32 + cc;
            const float4* ar = (const float4*)(aw + (size_t)ci * 512);
            float acc = 0.f;
#pragma unroll
            for (int m = 0; m < 4; ++m) {
                float4 v  = ar[lane + 32 * m];
                float4 s4 = ((const float4*)sw)[lane + 32 * m];
                acc += v.x * s4.x + v.y * s4.y + v.z * s4.z + v.w * s4.w;
            }
#pragma unroll
            for (int o = 16; o; o >>= 1) acc += __shfl_down_sync(~0u, acc, o);
            if (lane == 0) g_s[b * 512 + ci] = acc + ab[ci] + 1.0f;
        }
    } else {
        // prepw: g_Ah[tap][co][ci] = fp16(weight[co][ci][tap]); wsq = sum w^2
        const int co = bx - 16, ci = tid;
        const float* p = weight + ((size_t)co * 512 + ci) * 9;
        float sq = 0.f;
#pragma unroll
        for (int t = 0; t < 9; ++t) {
            float v = p[t];
            g_Ah[((size_t)t * 512 + co) * 512 + ci] = __float2half_rn(v);
            sq += v * v;
        }
        g_wsq[(size_t)co * 512 + ci] = sq;
    }
}

// ---------------------------------------------------------------------------
// Launch 2: prepx (x=0..33) + guard & y-border zero (x==34) + demod (x==35)
__global__ __launch_bounds__(512) void k_px(const float* __restrict__ x) {
    __shared__ float xt[256][33];
    const int r = blockIdx.x;
    const int b = blockIdx.y;
    const int tid = threadIdx.x;

    if (r == 35) {
        // demod: d[b,co] = rsqrt(sum_ci s^2 * wsq + 1e-8), coalesced
        __shared__ float s2[CIN_];
        {
            float v = g_s[b * CIN_ + tid];
            s2[tid] = v * v;
        }
        __syncthreads();
        const int lane = tid & 31, wp = tid >> 5;   // 16 warps x 32 co
        for (int cc = 0; cc < 32; ++cc) {
            const int co = wp * 32 + cc;
            const float4* wq = (const float4*)(g_wsq + (size_t)co * 512);
            float acc = 0.f;
#pragma unroll
            for (int m = 0; m < 4; ++m) {
                float4 v  = wq[lane + 32 * m];
                float4 s4 = ((const float4*)s2)[lane + 32 * m];
                acc += v.x * s4.x + v.y * s4.y + v.z * s4.z + v.w * s4.w;
            }
#pragma unroll
            for (int o = 16; o; o >>= 1) acc += __shfl_down_sync(~0u, acc, o);
            if (lane == 0) g_d[b * COUT_ + co] = rsqrtf(acc + 1e-8f);
        }
        return;
    }
    if (r == 34) {
        // guard zeroing: slice b of the 196608 guard halves
        const __half z = __float2half_rn(0.f);
        const int base = b * 12288;
        for (int k = tid; k < 12288; k += 512) {
            int idx = base + k;
            if (idx < XGUARD * 512)
                g_Xh[idx] = z;
            else
                g_Xh[(size_t)(XGUARD + XROWS) * 512 + (idx - XGUARD * 512)] = z;
        }
        // y-image border zero (row 0 full width; col 0 rows 1..66) for this b.
        // GEMM never writes these cells; blur reads them as zeros.
        const __half2 z2 = __floats2half2_rn(0.f, 0.f);
        for (int t = tid; t < 512 * 100; t += 512) {
            int co = t / 100, k = t - co * 100;
            __half* ib = g_y + ((size_t)(b * 512 + co)) * IMG_;
            if (k < 34) ((__half2*)ib)[k] = z2;      // row 0, cols 2k,2k+1
            else ib[(k - 33) * 68] = z;              // col 0, rows 1..66
        }
        return;
    }

    // prepx: row n = b*1156 + r*34 + c ; Xp = x*s interior, 0 on r,c in {0,33}
    const bool irow = (r >= 1 && r <= 32);
    for (int half = 0; half < 2; ++half) {
        const int cb = half * 256;
        __syncthreads();
        if (irow) {
            for (int idx = tid; idx < 256 * 32; idx += 512) {
                int ci = idx >> 5, cc = idx & 31;
                xt[ci][cc] = x[((size_t)(b * 512 + cb + ci) * 32 + (r - 1)) * 32 + cc]
                             * g_s[b * 512 + cb + ci];
            }
        }
        __syncthreads();
        for (int idx = tid; idx < 34 * 256; idx += 512) {
            int c = idx >> 8, ci = idx & 255;
            float v = (irow && c >= 1 && c <= 32) ? xt[ci][c - 1] : 0.f;
            size_t o = ((size_t)(b * 1156 + r * 34 + c) + XGUARD) * 512 + cb + ci;
            g_Xh[o] = __float2half_rn(v);
        }
    }
}

// ---------------------------------------------------------------------------
// Launch 3: GEMM. Mainloop identical to champion; epilogue writes the
// interleaved image directly: n=(b,i',j'), parity p=(a,c) -> cell
// (2i'+a-1, 2j'+c-1). i'=0 / j'=0 values are exactly zero (Xp border) and
// are discarded; border cells come from the k_px zeroing.
#define STAGES      4
#define TILE_A      0           // 128 x 64 fp16 = 16KB
#define TILE_B      16384       // 256 x 64 fp16 = 32KB
#define STAGE_BYTES 49152
#define NCHUNK      72          // 9 taps x 8 chunks of 64 ci

__device__ __forceinline__ void load_chunk(uint32_t su, int stage, int g,
                                           int co0, int n0, int tid) {
    const int tap = c_tap[g >> 3];
    const int kc  = (g & 7) << 6;
    const uint32_t sb = su + stage * STAGE_BYTES;
#pragma unroll
    for (int t = 0; t < 4; ++t) {
        int idx = t * 256 + tid;
        int row = idx >> 3, c8 = idx & 7;
        size_t aoff = ((size_t)(tap * 512 + co0 + row)) * 512 + kc + c8 * 8;
        cp16(sb + TILE_A + swz(row, c8), g_Ah + aoff);
    }
    const long base = (long)n0 - c_shift[tap] + XGUARD;
#pragma unroll
    for (int t = 0; t < 8; ++t) {
        int idx = t * 256 + tid;
        int row = idx >> 3, c8 = idx & 7;
        size_t boff = (size_t)(base + row) * 512 + kc + c8 * 8;
        cp16(sb + TILE_B + swz(row, c8), g_Xh + boff);
    }
}

__device__ __forceinline__ void do_compute(uint32_t sb, float acc[4][8][4],
                                           int lane, int warp_m, int warp_n) {
#pragma unroll
    for (int ks = 0; ks < 4; ++ks) {
        uint32_t bh[16];
#pragma unroll
        for (int pr = 0; pr < 4; ++pr) {
            int brow = warp_n + pr * 16 + (lane & 7) + ((lane >> 4) & 1) * 8;
            int bc8  = ks * 2 + ((lane >> 3) & 1);
            ldsm_x4(&bh[pr * 4], sb + TILE_B + swz(brow, bc8));
        }
#pragma unroll
        for (int mt = 0; mt < 4; ++mt) {
            int arow = warp_m + mt * 16 + (lane & 15);
            int ac8  = ks * 2 + ((lane >> 4) & 1);
            uint32_t ah[4];
            ldsm_x4(ah, sb + TILE_A + swz(arow, ac8));
#pragma unroll
            for (int nt = 0; nt < 8; ++nt) {
                mma_fp16(acc[mt][nt], ah, &bh[(nt >> 1) * 4 + (nt & 1) * 2]);
            }
        }
    }
}

__device__ __forceinline__ void epilogue(float acc[4][8][4], int p, int co0,
                                         int n0, int lane, int warp_m, int warp_n) {
    const int rr = lane >> 2, q = lane & 3;
    const int a = p >> 1, c = p & 1;
#pragma unroll
    for (int mt = 0; mt < 4; ++mt) {
        const int co = co0 + warp_m + mt * 16 + rr;
#pragma unroll
        for (int nt = 0; nt < 8; ++nt) {
            int n = n0 + warp_n + nt * 8 + q * 2;
            if (n < XROWS) {
                int b   = n / 1156;
                int rem = n - b * 1156;
                int ip  = rem / 34;
                int jp  = rem - ip * 34;
                if (ip >= 1) {
                    int off = (2 * ip + a - 1) * 68 + (2 * jp + c - 1);
                    __half* i0 = g_y + ((size_t)(b * 512 + co)) * IMG_ + off;
                    __half* i1 = g_y + ((size_t)(b * 512 + co + 8)) * IMG_ + off;
                    if (jp >= 1) {
                        i0[0] = __float2half_rn(acc[mt][nt][0]);
                        i1[0] = __float2half_rn(acc[mt][nt][2]);
                    }
                    if (jp <= 32) {
                        i0[2] = __float2half_rn(acc[mt][nt][1]);
                        i1[2] = __float2half_rn(acc[mt][nt][3]);
                    }
                }
            }
        }
    }
}

__global__ __launch_bounds__(256, 1) void k_gemm() {
    extern __shared__ char smem[];
    const uint32_t su = smem_to_u32(smem);
    const int tid = threadIdx.x;
    const int lane = tid & 31, wid = tid >> 5;
    const int warp_m = (wid >> 2) * 64;
    const int warp_n = (wid & 3) * 64;
    const int n0  = blockIdx.x * 256;
    const int co0 = blockIdx.y * 128;

    float acc[4][8][4];
#pragma unroll
    for (int a = 0; a < 4; ++a)
#pragma unroll
        for (int b = 0; b < 8; ++b)
#pragma unroll
            for (int c = 0; c < 4; ++c) acc[a][b][c] = 0.f;

#pragma unroll
    for (int s = 0; s < STAGES - 1; ++s) {
        load_chunk(su, s, s, co0, n0, tid);
        cp_commit();
    }

    for (int g = 0; g < NCHUNK; ++g) {
        cp_wait2();
        __syncthreads();
        if (g + STAGES - 1 < NCHUNK)
            load_chunk(su, (g + STAGES - 1) % STAGES, g + STAGES - 1, co0, n0, tid);
        cp_commit();
        do_compute(su + (g % STAGES) * STAGE_BYTES, acc, lane, warp_m, warp_n);
        if (g == 31 || g == 47 || g == 63 || g == 71) {
            const int p = (g == 31) ? 0 : (g == 47) ? 1 : (g == 63) ? 2 : 3;
            epilogue(acc, p, co0, n0, lane, warp_m, warp_n);
#pragma unroll
            for (int a = 0; a < 4; ++a)
#pragma unroll
                for (int b = 0; b < 8; ++b)
#pragma unroll
                    for (int c = 0; c < 4; ++c) acc[a][b][c] = 0.f;
        }
    }
}

// ---------------------------------------------------------------------------
// Launch 4 (profiled): blur v4 — no demux. Straight half4->float4 copy of the
// interleaved image, then register-streamed vertical+horizontal (as v3).
__global__ __launch_bounds__(256, 6) void k_blur(float* __restrict__ z,
                                                 const float* __restrict__ bias) {
    __shared__ float ys[67][68];
    const int co = blockIdx.x, b = blockIdx.y;
    const int tid = threadIdx.x;

    const __half* yb = g_y + ((size_t)(b * 512 + co)) * IMG_;
    for (int item = tid; item < 67 * 17; item += 256) {   // rows 0..66, 17 x half4
        int r = item / 17, k = item - r * 17;
        uint2 raw = *(const uint2*)(yb + r * 68 + 4 * k);
        float2 f0 = __half22float2(*(__half2*)&raw.x);
        float2 f1 = __half22float2(*(__half2*)&raw.y);
        *(float4*)&ys[r][4 * k] = make_float4(f0.x, f0.y, f1.x, f1.y);
    }
    __syncthreads();

    const float scale = g_d[b * COUT_ + co] * (1.f / 16.f);
    const float bv = bias[co];
    const int u  = tid >> 2;          // 0..63
    const int v0 = (tid & 3) * 16;    // 16 outputs per thread

    float4* zp = (float4*)(z + (((size_t)b * COUT_ + co) * 64 + u) * 64 + v0);

    float cprev[4];
#pragma unroll
    for (int q = 0; q < 5; ++q) {
        float4 r0 = *(const float4*)&ys[u][v0 + 4 * q];
        float4 r1 = *(const float4*)&ys[u + 1][v0 + 4 * q];
        float4 r2 = *(const float4*)&ys[u + 2][v0 + 4 * q];
        float4 r3 = *(const float4*)&ys[u + 3][v0 + 4 * q];
        float ccur[4];
        ccur[0] = (r0.x + r3.x) + 3.f * (r1.x + r2.x);
        ccur[1] = (r0.y + r3.y) + 3.f * (r1.y + r2.y);
        ccur[2] = (r0.z + r3.z) + 3.f * (r1.z + r2.z);
        ccur[3] = (r0.w + r3.w) + 3.f * (r1.w + r2.w);
        if (q > 0) {
            float wv[8] = {cprev[0], cprev[1], cprev[2], cprev[3],
                           ccur[0],  ccur[1],  ccur[2],  ccur[3]};
            float4 o;
            o.x = fmaf((wv[0] + wv[3]) + 3.f * (wv[1] + wv[2]), scale, bv);
            o.y = fmaf((wv[1] + wv[4]) + 3.f * (wv[2] + wv[3]), scale, bv);
            o.z = fmaf((wv[2] + wv[5]) + 3.f * (wv[3] + wv[4]), scale, bv);
            o.w = fmaf((wv[3] + wv[6]) + 3.f * (wv[4] + wv[5]), scale, bv);
            zp[q - 1] = o;
        }
#pragma unroll
        for (int e = 0; e < 4; ++e) cprev[e] = ccur[e];
    }
}

// ---------------------------------------------------------------------------
extern "C" void kernel_launch(void* const* d_in, const int* in_sizes, int n_in,
                              void* d_out, int out_size) {
    const float* x    = (const float*)d_in[0];
    const float* w    = (const float*)d_in[1];
    const float* wt   = (const float*)d_in[2];
    const float* bias = (const float*)d_in[3];
    const float* aw   = (const float*)d_in[4];
    const float* ab   = (const float*)d_in[5];
    float* z = (float*)d_out;

    cudaFuncSetAttribute(k_gemm, cudaFuncAttributeMaxDynamicSharedMemorySize,
                         STAGES * STAGE_BYTES);

    // 4 launches; k_blur 4th -> ncu profiles it (verify blur v4).
    k_sw<<<16 + COUT_, 512>>>(w, aw, ab, wt);               // 1
    k_px<<<dim3(36, B_), 512>>>(x);                         // 2
    k_gemm<<<dim3(NT2, 4), 256, STAGES * STAGE_BYTES>>>();  // 3
    k_blur<<<dim3(COUT_, B_), 256>>>(z, bias);              // 4  <- profiled
}